// round 6
// baseline (speedup 1.0000x reference)
#include <cuda_runtime.h>
#include <math.h>

// Problem constants (shapes are fixed by the reference)
#define NMAX 100000
#define EMAX 1600000
#define FDIM 64
#define CDIM 40

typedef unsigned long long u64;

// ---------------------------------------------------------------------------
// Scratch (device globals — no runtime allocation allowed)
// ---------------------------------------------------------------------------
__device__ __align__(16) float g_agg[NMAX * FDIM];  // scatter accumulator
__device__ __align__(16) float g_h1 [NMAX * FDIM];  // layer1 output
__device__ __align__(16) float g_h2 [NMAX * FDIM];  // layer2 output
__device__ float g_inv[NMAX];                        // degree -> 1/max(deg,1)

// ---------------------------------------------------------------------------
// f32x2 packed-FMA helpers (Blackwell: fma.rn.f32x2, 2x FFMA throughput)
// ---------------------------------------------------------------------------
__device__ __forceinline__ u64 pack2(float lo, float hi) {
    u64 r;
    asm("mov.b64 %0, {%1, %2};" : "=l"(r) : "f"(lo), "f"(hi));
    return r;
}
__device__ __forceinline__ void fma2(u64& d, u64 a, u64 b) {
    asm("fma.rn.f32x2 %0, %1, %2, %0;" : "+l"(d) : "l"(a), "l"(b));
}
__device__ __forceinline__ float hsum2(u64 v) {
    float lo, hi;
    asm("mov.b64 {%0, %1}, %2;" : "=f"(lo), "=f"(hi) : "l"(v));
    return lo + hi;
}

// ---------------------------------------------------------------------------
// Utility kernels
// ---------------------------------------------------------------------------
__global__ void zero_kernel(float4* __restrict__ p, int n4) {
    int i = blockIdx.x * blockDim.x + threadIdx.x;
    if (i < n4) p[i] = make_float4(0.f, 0.f, 0.f, 0.f);
}

__global__ void deg_kernel(const int* __restrict__ dst, float* __restrict__ deg, int E) {
    int e = blockIdx.x * blockDim.x + threadIdx.x;
    if (e < E) atomicAdd(&deg[dst[e]], 1.0f);   // emits RED.ADD (no return use)
}

__global__ void inv_kernel(float* __restrict__ inv, int n) {
    int i = blockIdx.x * blockDim.x + threadIdx.x;
    if (i < n) inv[i] = 1.0f / fmaxf(inv[i], 1.0f);
}

// ---------------------------------------------------------------------------
// Scatter: agg[dst] += x[src]   (16 threads per edge, one float4 each,
// fire-and-forget v4 atomics -> pure L2 traffic, no return path)
// ---------------------------------------------------------------------------
__global__ void scatter_kernel(const float4* __restrict__ xin,
                               const int* __restrict__ src,
                               const int* __restrict__ dst,
                               float4* __restrict__ agg, int E) {
    int idx = blockIdx.x * blockDim.x + threadIdx.x;
    if (idx >= E * 16) return;
    int e = idx >> 4;
    int q = idx & 15;
    int s = __ldg(&src[e]);
    int d = __ldg(&dst[e]);
    float4 v = __ldg(&xin[s * 16 + q]);
    const float4* p = &agg[d * 16 + q];
    asm volatile("red.global.add.v4.f32 [%0], {%1, %2, %3, %4};"
                 :: "l"(p), "f"(v.x), "f"(v.y), "f"(v.z), "f"(v.w)
                 : "memory");
}

// ---------------------------------------------------------------------------
// Fused dense layer: out[i] = act( (agg[i]*inv[i]) @ Wl^T + b + xin[i] @ Wr^T )
// Thread = one output column j for 4 consecutive nodes (register blocking).
// Weights in SMEM transposed [k][OUT] (conflict-free LDS across j-lanes);
// rows staged in SMEM and read as broadcast LDS.64 k-pairs; packed f32x2 FMAs.
// ---------------------------------------------------------------------------
template <int OUT, int NG, bool RELU>
__launch_bounds__(OUT * NG)
__global__ void gemm_kernel(const float* __restrict__ agg,
                            const float* __restrict__ xin,
                            const float* __restrict__ inv,
                            const float* __restrict__ Wl,
                            const float* __restrict__ Wr,
                            const float* __restrict__ bias,
                            float* __restrict__ out, int nNodes) {
    constexpr int NT   = OUT * NG;   // threads per block
    constexpr int TILE = NG * 4;     // nodes per tile

    __shared__ float sWl[64 * OUT];
    __shared__ float sWr[64 * OUT];
    __shared__ __align__(16) float sA[TILE * 64];
    __shared__ __align__(16) float sX[TILE * 64];

    const int tid = threadIdx.x;

    // Stage transposed weights once per block: sW[k*OUT + j] = W[j*64 + k]
    for (int idx = tid; idx < 64 * OUT; idx += NT) {
        int k = idx / OUT;
        int j = idx - k * OUT;
        sWl[idx] = Wl[j * 64 + k];
        sWr[idx] = Wr[j * 64 + k];
    }

    const int j = tid % OUT;
    const int g = tid / OUT;
    const float bj = __ldg(&bias[j]);

    const int nTiles = (nNodes + TILE - 1) / TILE;
    for (int t = blockIdx.x; t < nTiles; t += gridDim.x) {
        __syncthreads();  // protect SMEM reuse across tiles (covers weight stage too)
        const int base = t * TILE;

        // Stage rows: mean-scale agg at load time
        for (int idx = tid; idx < TILE * 64; idx += NT) {
            int n = idx >> 6;
            int k = idx & 63;
            int node = base + n;
            float a = 0.f, xx = 0.f;
            if (node < nNodes) {
                a  = agg[node * 64 + k] * inv[node];
                xx = xin[node * 64 + k];
            }
            sA[idx] = a;
            sX[idx] = xx;
        }
        __syncthreads();

        u64 acc0 = 0, acc1 = 0, acc2 = 0, acc3 = 0;
        const float* pa = &sA[(g * 4) * 64];
        const float* px = &sX[(g * 4) * 64];

#pragma unroll
        for (int k = 0; k < 64; k += 2) {
            u64 wl = pack2(sWl[k * OUT + j], sWl[(k + 1) * OUT + j]);
            u64 wr = pack2(sWr[k * OUT + j], sWr[(k + 1) * OUT + j]);
            fma2(acc0, *(const u64*)(pa + 0 * 64 + k), wl);
            fma2(acc0, *(const u64*)(px + 0 * 64 + k), wr);
            fma2(acc1, *(const u64*)(pa + 1 * 64 + k), wl);
            fma2(acc1, *(const u64*)(px + 1 * 64 + k), wr);
            fma2(acc2, *(const u64*)(pa + 2 * 64 + k), wl);
            fma2(acc2, *(const u64*)(px + 2 * 64 + k), wr);
            fma2(acc3, *(const u64*)(pa + 3 * 64 + k), wl);
            fma2(acc3, *(const u64*)(px + 3 * 64 + k), wr);
        }

        float r0 = hsum2(acc0) + bj;
        float r1 = hsum2(acc1) + bj;
        float r2 = hsum2(acc2) + bj;
        float r3 = hsum2(acc3) + bj;
        if (RELU) {
            r0 = fmaxf(r0, 0.f); r1 = fmaxf(r1, 0.f);
            r2 = fmaxf(r2, 0.f); r3 = fmaxf(r3, 0.f);
        }
        const int n0 = base + g * 4;
        if (n0 + 0 < nNodes) out[(n0 + 0) * OUT + j] = r0;
        if (n0 + 1 < nNodes) out[(n0 + 1) * OUT + j] = r1;
        if (n0 + 2 < nNodes) out[(n0 + 2) * OUT + j] = r2;
        if (n0 + 3 < nNodes) out[(n0 + 3) * OUT + j] = r3;
    }
}

// ---------------------------------------------------------------------------
// In-place log_softmax over rows of 40 (one warp per row, shfl reductions)
// ---------------------------------------------------------------------------
__global__ void lsm_kernel(float* __restrict__ out, int n) {
    int w    = (blockIdx.x * blockDim.x + threadIdx.x) >> 5;
    int lane = threadIdx.x & 31;
    if (w >= n) return;
    float* row = out + (size_t)w * CDIM;

    float v0 = (lane < CDIM)      ? row[lane]      : -3.4e38f;
    float v1 = (lane + 32 < CDIM) ? row[lane + 32] : -3.4e38f;

    float m = fmaxf(v0, v1);
#pragma unroll
    for (int o = 16; o; o >>= 1) m = fmaxf(m, __shfl_xor_sync(0xffffffffu, m, o));

    float s = ((lane < CDIM) ? expf(v0 - m) : 0.f) +
              ((lane + 32 < CDIM) ? expf(v1 - m) : 0.f);
#pragma unroll
    for (int o = 16; o; o >>= 1) s += __shfl_xor_sync(0xffffffffu, s, o);

    float l = m + logf(s);
    if (lane < CDIM)      row[lane]      = v0 - l;
    if (lane + 32 < CDIM) row[lane + 32] = v1 - l;
}

// ---------------------------------------------------------------------------
// kernel_launch: 3x (zero -> scatter -> fused gemm) + degree prep + logsoftmax
// ---------------------------------------------------------------------------
extern "C" void kernel_launch(void* const* d_in, const int* in_sizes, int n_in,
                              void* d_out, int out_size) {
    const float* x   = (const float*)d_in[0];
    const int*   ei  = (const int*)d_in[1];
    const float* Wl1 = (const float*)d_in[2];
    const float* Wr1 = (const float*)d_in[3];
    const float* b1  = (const float*)d_in[4];
    const float* Wl2 = (const float*)d_in[5];
    const float* Wr2 = (const float*)d_in[6];
    const float* b2  = (const float*)d_in[7];
    const float* Wl3 = (const float*)d_in[8];
    const float* Wr3 = (const float*)d_in[9];
    const float* b3  = (const float*)d_in[10];
    float* out = (float*)d_out;

    const int N = in_sizes[0] / FDIM;
    const int E = in_sizes[1] / 2;
    const int* src = ei;
    const int* dst = ei + E;

    float *agg, *h1, *h2, *inv;
    cudaGetSymbolAddress((void**)&agg, g_agg);
    cudaGetSymbolAddress((void**)&h1,  g_h1);
    cudaGetSymbolAddress((void**)&h2,  g_h2);
    cudaGetSymbolAddress((void**)&inv, g_inv);

    const int nf4   = (N * FDIM) / 4;                 // agg zero size in float4
    const int zaggB = (nf4 + 255) / 256;
    const int zinvB = ((N + 3) / 4 + 255) / 256;
    const int degB  = (E + 255) / 256;
    const int invB  = (N + 255) / 256;
    const int scatB = (E * 16 + 255) / 256;
    const int gemmB = 1480;                           // grid-stride over node tiles
    const int lsmB  = (N * 32 + 255) / 256;

    // Degrees -> reciprocal (shared by all 3 layers)
    zero_kernel<<<zinvB, 256>>>((float4*)inv, (N + 3) / 4);
    deg_kernel<<<degB, 256>>>(dst, inv, E);
    inv_kernel<<<invB, 256>>>(inv, N);

    // Layer 1: x -> h1 (relu)
    zero_kernel<<<zaggB, 256>>>((float4*)agg, nf4);
    scatter_kernel<<<scatB, 256>>>((const float4*)x, src, dst, (float4*)agg, E);
    gemm_kernel<64, 4, true><<<gemmB, 256>>>(agg, x, inv, Wl1, Wr1, b1, h1, N);

    // Layer 2: h1 -> h2 (relu)
    zero_kernel<<<zaggB, 256>>>((float4*)agg, nf4);
    scatter_kernel<<<scatB, 256>>>((const float4*)h1, src, dst, (float4*)agg, E);
    gemm_kernel<64, 4, true><<<gemmB, 256>>>(agg, h1, inv, Wl2, Wr2, b2, h2, N);

    // Layer 3: h2 -> logits (no relu), then in-place log_softmax
    zero_kernel<<<zaggB, 256>>>((float4*)agg, nf4);
    scatter_kernel<<<scatB, 256>>>((const float4*)h2, src, dst, (float4*)agg, E);
    gemm_kernel<40, 6, false><<<gemmB, 240>>>(agg, h2, inv, Wl3, Wr3, b3, out, N);

    lsm_kernel<<<lsmB, 256>>>(out, N);
}

// round 7
// speedup vs baseline: 1.7295x; 1.7295x over previous
#include <cuda_runtime.h>
#include <math.h>

#define NMAX 100000
#define EMAX 1600000
#define CDIM 40

typedef unsigned long long u64;

// ---------------------------------------------------------------------------
// Scratch (device globals — no runtime allocation allowed)
// ---------------------------------------------------------------------------
__device__ __align__(16) float g_h1[NMAX * 64];
__device__ __align__(16) float g_h2[NMAX * 64];
__device__ int g_deg[NMAX];     // in-degree per node
__device__ int g_cur[NMAX];     // fill cursors
__device__ int g_start[NMAX];   // per-block-local exclusive scan of deg
__device__ int g_spine[1024];   // exclusive scan of 1024-chunk totals
__device__ int g_col[EMAX];     // CSR column (src) indices grouped by dst

// ---------------------------------------------------------------------------
// f32x2 packed-FMA helpers (Blackwell fma.rn.f32x2: 2 FMAs per issue)
// ---------------------------------------------------------------------------
__device__ __forceinline__ u64 pack2(float lo, float hi) {
    u64 r;
    asm("mov.b64 %0, {%1, %2};" : "=l"(r) : "f"(lo), "f"(hi));
    return r;
}
__device__ __forceinline__ void fma2(u64& d, u64 a, u64 b) {
    asm("fma.rn.f32x2 %0, %1, %2, %0;" : "+l"(d) : "l"(a), "l"(b));
}
__device__ __forceinline__ float hsum2(u64 v) {
    float lo, hi;
    asm("mov.b64 {%0, %1}, %2;" : "=f"(lo), "=f"(hi) : "l"(v));
    return lo + hi;
}

// ---------------------------------------------------------------------------
// CSR build kernels
// ---------------------------------------------------------------------------
__global__ void zero_int2_kernel(int* __restrict__ a, int* __restrict__ b, int n) {
    int i = blockIdx.x * blockDim.x + threadIdx.x;
    if (i < n) { a[i] = 0; b[i] = 0; }
}

__global__ void hist_kernel(const int* __restrict__ dst, int* __restrict__ deg, int E) {
    int e = blockIdx.x * blockDim.x + threadIdx.x;
    if (e < E) atomicAdd(&deg[dst[e]], 1);
}

// Per-1024-block exclusive scan; block totals to part[]
__global__ void scan1_kernel(const int* __restrict__ deg, int* __restrict__ start,
                             int* __restrict__ part, int n) {
    int t = threadIdx.x;
    int gid = blockIdx.x * 1024 + t;
    int v = (gid < n) ? deg[gid] : 0;
    int lane = t & 31, w = t >> 5;
    int inc = v;
#pragma unroll
    for (int o = 1; o < 32; o <<= 1) {
        int u = __shfl_up_sync(0xffffffffu, inc, o);
        if (lane >= o) inc += u;
    }
    __shared__ int ws[32];
    if (lane == 31) ws[w] = inc;
    __syncthreads();
    if (t < 32) {
        int s = ws[t];
#pragma unroll
        for (int o = 1; o < 32; o <<= 1) {
            int u = __shfl_up_sync(0xffffffffu, s, o);
            if (t >= o) s += u;
        }
        ws[t] = s;
    }
    __syncthreads();
    int offs = (w > 0) ? ws[w - 1] : 0;
    if (gid < n) start[gid] = offs + inc - v;   // block-local exclusive
    if (t == 0) part[blockIdx.x] = ws[31];      // block total
}

// Exclusive scan of block totals (nb <= 1024), in place
__global__ void spine_kernel(int* __restrict__ part, int nb) {
    int t = threadIdx.x;
    int v = (t < nb) ? part[t] : 0;
    int lane = t & 31, w = t >> 5;
    int inc = v;
#pragma unroll
    for (int o = 1; o < 32; o <<= 1) {
        int u = __shfl_up_sync(0xffffffffu, inc, o);
        if (lane >= o) inc += u;
    }
    __shared__ int ws[32];
    if (lane == 31) ws[w] = inc;
    __syncthreads();
    if (t < 32) {
        int s = ws[t];
#pragma unroll
        for (int o = 1; o < 32; o <<= 1) {
            int u = __shfl_up_sync(0xffffffffu, s, o);
            if (t >= o) s += u;
        }
        ws[t] = s;
    }
    __syncthreads();
    int offs = (w > 0) ? ws[w - 1] : 0;
    if (t < nb) part[t] = offs + inc - v;       // exclusive prefix of totals
}

__global__ void fill_kernel(const int* __restrict__ src, const int* __restrict__ dst,
                            const int* __restrict__ start, const int* __restrict__ spine,
                            int* __restrict__ cur, int* __restrict__ col, int E) {
    int e = blockIdx.x * blockDim.x + threadIdx.x;
    if (e >= E) return;
    int d = dst[e];
    int p = start[d] + spine[d >> 10] + atomicAdd(&cur[d], 1);
    col[p] = src[e];
}

// ---------------------------------------------------------------------------
// Fused layer: gather-mean neighbors (CSR) + out = agg@Wl^T + x@Wr^T + b (+relu)
// Tile = 32 nodes, 256 threads. Gather: 8 thr/node, 2 float4 chunks each.
// GEMM: thread = (j, j+32) x 4 nodes; weights prepacked as k-pair u64 in SMEM.
// ---------------------------------------------------------------------------
template <int OUTS, bool RELU>
__launch_bounds__(256)
__global__ void layer_kernel(const float4* __restrict__ xin4,
                             const int* __restrict__ start,
                             const int* __restrict__ spine,
                             const int* __restrict__ deg,
                             const int* __restrict__ col,
                             const float* __restrict__ Wl,
                             const float* __restrict__ Wr,
                             const float* __restrict__ bias,
                             float* __restrict__ out, int nN) {
    __shared__ u64 sWl[32 * 64];                 // [kp][j] = (Wl[j][2kp], Wl[j][2kp+1])
    __shared__ u64 sWr[32 * 64];
    __shared__ __align__(16) float sA[32 * 64];  // mean-aggregated rows
    __shared__ __align__(16) float sX[32 * 64];  // self rows

    const int tid = threadIdx.x;

    // Stage prepacked weights (zero-pad rows j >= OUTS)
    for (int idx = tid; idx < 2048; idx += 256) {
        int kp = idx >> 6;
        int j  = idx & 63;
        float l0 = 0.f, l1 = 0.f, r0 = 0.f, r1 = 0.f;
        if (j < OUTS) {
            l0 = Wl[j * 64 + 2 * kp]; l1 = Wl[j * 64 + 2 * kp + 1];
            r0 = Wr[j * 64 + 2 * kp]; r1 = Wr[j * 64 + 2 * kp + 1];
        }
        sWl[idx] = pack2(l0, l1);
        sWr[idx] = pack2(r0, r1);
    }

    const int j  = tid & 31;
    const int g  = tid >> 5;   // node group 0..7 (4 nodes each)
    const int gn = tid >> 3;   // gather node in tile 0..31
    const int q  = tid & 7;    // float4 chunk
    const float bj0 = (j < OUTS) ? __ldg(&bias[j]) : 0.f;
    const float bj1 = (j + 32 < OUTS) ? __ldg(&bias[j + 32]) : 0.f;

    const int nTiles = (nN + 31) >> 5;
    for (int t = blockIdx.x; t < nTiles; t += gridDim.x) {
        __syncthreads();   // protect SMEM reuse (covers weight stage on first iter)
        const int base = t << 5;
        const int node = base + gn;

        float4 a0 = {0, 0, 0, 0}, a1 = {0, 0, 0, 0};
        float4 x0 = {0, 0, 0, 0}, x1 = {0, 0, 0, 0};
        if (node < nN) {
            const int d = __ldg(&deg[node]);
            const int p = __ldg(&start[node]) + __ldg(&spine[node >> 10]);
            int i = 0;
            for (; i + 2 <= d; i += 2) {            // unroll 2 for MLP
                int n0 = __ldg(&col[p + i]);
                int n1 = __ldg(&col[p + i + 1]);
                float4 v00 = __ldg(xin4 + n0 * 16 + q);
                float4 v01 = __ldg(xin4 + n0 * 16 + q + 8);
                float4 v10 = __ldg(xin4 + n1 * 16 + q);
                float4 v11 = __ldg(xin4 + n1 * 16 + q + 8);
                a0.x += v00.x + v10.x; a0.y += v00.y + v10.y;
                a0.z += v00.z + v10.z; a0.w += v00.w + v10.w;
                a1.x += v01.x + v11.x; a1.y += v01.y + v11.y;
                a1.z += v01.z + v11.z; a1.w += v01.w + v11.w;
            }
            if (i < d) {
                int n0 = __ldg(&col[p + i]);
                float4 v00 = __ldg(xin4 + n0 * 16 + q);
                float4 v01 = __ldg(xin4 + n0 * 16 + q + 8);
                a0.x += v00.x; a0.y += v00.y; a0.z += v00.z; a0.w += v00.w;
                a1.x += v01.x; a1.y += v01.y; a1.z += v01.z; a1.w += v01.w;
            }
            float iv = 1.0f / fmaxf((float)d, 1.0f);
            a0.x *= iv; a0.y *= iv; a0.z *= iv; a0.w *= iv;
            a1.x *= iv; a1.y *= iv; a1.z *= iv; a1.w *= iv;
            x0 = __ldg(xin4 + node * 16 + q);
            x1 = __ldg(xin4 + node * 16 + q + 8);
        }
        ((float4*)sA)[gn * 16 + q]     = a0;
        ((float4*)sA)[gn * 16 + q + 8] = a1;
        ((float4*)sX)[gn * 16 + q]     = x0;
        ((float4*)sX)[gn * 16 + q + 8] = x1;
        __syncthreads();

        u64 acc00 = 0, acc01 = 0, acc02 = 0, acc03 = 0;
        u64 acc10 = 0, acc11 = 0, acc12 = 0, acc13 = 0;
        const u64* pA = (const u64*)sA + (g * 4) * 32;
        const u64* pX = (const u64*)sX + (g * 4) * 32;

#pragma unroll 8
        for (int kp = 0; kp < 32; kp++) {
            u64 wl0 = sWl[kp * 64 + j];
            u64 wl1 = sWl[kp * 64 + j + 32];
            u64 wr0 = sWr[kp * 64 + j];
            u64 wr1 = sWr[kp * 64 + j + 32];
            u64 av0 = pA[kp], av1 = pA[32 + kp], av2 = pA[64 + kp], av3 = pA[96 + kp];
            u64 xv0 = pX[kp], xv1 = pX[32 + kp], xv2 = pX[64 + kp], xv3 = pX[96 + kp];
            fma2(acc00, av0, wl0); fma2(acc00, xv0, wr0);
            fma2(acc01, av1, wl0); fma2(acc01, xv1, wr0);
            fma2(acc02, av2, wl0); fma2(acc02, xv2, wr0);
            fma2(acc03, av3, wl0); fma2(acc03, xv3, wr0);
            fma2(acc10, av0, wl1); fma2(acc10, xv0, wr1);
            fma2(acc11, av1, wl1); fma2(acc11, xv1, wr1);
            fma2(acc12, av2, wl1); fma2(acc12, xv2, wr1);
            fma2(acc13, av3, wl1); fma2(acc13, xv3, wr1);
        }

        float r00 = hsum2(acc00) + bj0, r01 = hsum2(acc01) + bj0;
        float r02 = hsum2(acc02) + bj0, r03 = hsum2(acc03) + bj0;
        float r10 = hsum2(acc10) + bj1, r11 = hsum2(acc11) + bj1;
        float r12 = hsum2(acc12) + bj1, r13 = hsum2(acc13) + bj1;
        if (RELU) {
            r00 = fmaxf(r00, 0.f); r01 = fmaxf(r01, 0.f);
            r02 = fmaxf(r02, 0.f); r03 = fmaxf(r03, 0.f);
            r10 = fmaxf(r10, 0.f); r11 = fmaxf(r11, 0.f);
            r12 = fmaxf(r12, 0.f); r13 = fmaxf(r13, 0.f);
        }
        const int n0 = base + g * 4;
        const bool hi = (j + 32 < OUTS);
        if (n0 + 0 < nN) { out[(n0 + 0) * OUTS + j] = r00; if (hi) out[(n0 + 0) * OUTS + j + 32] = r10; }
        if (n0 + 1 < nN) { out[(n0 + 1) * OUTS + j] = r01; if (hi) out[(n0 + 1) * OUTS + j + 32] = r11; }
        if (n0 + 2 < nN) { out[(n0 + 2) * OUTS + j] = r02; if (hi) out[(n0 + 2) * OUTS + j + 32] = r12; }
        if (n0 + 3 < nN) { out[(n0 + 3) * OUTS + j] = r03; if (hi) out[(n0 + 3) * OUTS + j + 32] = r13; }
    }
}

// ---------------------------------------------------------------------------
// In-place log_softmax over rows of 40 (one warp per row)
// ---------------------------------------------------------------------------
__global__ void lsm_kernel(float* __restrict__ out, int n) {
    int w    = (blockIdx.x * blockDim.x + threadIdx.x) >> 5;
    int lane = threadIdx.x & 31;
    if (w >= n) return;
    float* row = out + (size_t)w * CDIM;

    float v0 = (lane < CDIM)      ? row[lane]      : -3.4e38f;
    float v1 = (lane + 32 < CDIM) ? row[lane + 32] : -3.4e38f;

    float m = fmaxf(v0, v1);
#pragma unroll
    for (int o = 16; o; o >>= 1) m = fmaxf(m, __shfl_xor_sync(0xffffffffu, m, o));

    float s = ((lane < CDIM) ? expf(v0 - m) : 0.f) +
              ((lane + 32 < CDIM) ? expf(v1 - m) : 0.f);
#pragma unroll
    for (int o = 16; o; o >>= 1) s += __shfl_xor_sync(0xffffffffu, s, o);

    float l = m + logf(s);
    if (lane < CDIM)      row[lane]      = v0 - l;
    if (lane + 32 < CDIM) row[lane + 32] = v1 - l;
}

// ---------------------------------------------------------------------------
// kernel_launch: CSR build (5 launches) + 3 fused layers + log_softmax
// (layer 1 is the 6th launch -> it is what ncu -s 5 -c 1 profiles)
// ---------------------------------------------------------------------------
extern "C" void kernel_launch(void* const* d_in, const int* in_sizes, int n_in,
                              void* d_out, int out_size) {
    const float* x   = (const float*)d_in[0];
    const int*   ei  = (const int*)d_in[1];
    const float* Wl1 = (const float*)d_in[2];
    const float* Wr1 = (const float*)d_in[3];
    const float* b1  = (const float*)d_in[4];
    const float* Wl2 = (const float*)d_in[5];
    const float* Wr2 = (const float*)d_in[6];
    const float* b2  = (const float*)d_in[7];
    const float* Wl3 = (const float*)d_in[8];
    const float* Wr3 = (const float*)d_in[9];
    const float* b3  = (const float*)d_in[10];
    float* out = (float*)d_out;

    const int N = in_sizes[0] / 64;
    const int E = in_sizes[1] / 2;
    const int* src = ei;
    const int* dst = ei + E;

    int *deg, *cur, *start, *spine, *col;
    float *h1, *h2;
    cudaGetSymbolAddress((void**)&deg,   g_deg);
    cudaGetSymbolAddress((void**)&cur,   g_cur);
    cudaGetSymbolAddress((void**)&start, g_start);
    cudaGetSymbolAddress((void**)&spine, g_spine);
    cudaGetSymbolAddress((void**)&col,   g_col);
    cudaGetSymbolAddress((void**)&h1,    g_h1);
    cudaGetSymbolAddress((void**)&h2,    g_h2);

    const int nScanB = (N + 1023) / 1024;
    const int edgeB  = (E + 255) / 256;
    const int layerB = 592;   // 4 blocks/SM * 148 SMs, grid-stride over tiles

    // CSR build (launches 1-5)
    zero_int2_kernel<<<(N + 255) / 256, 256>>>(deg, cur, N);
    hist_kernel<<<edgeB, 256>>>(dst, deg, E);
    scan1_kernel<<<nScanB, 1024>>>(deg, start, spine, N);
    spine_kernel<<<1, 1024>>>(spine, nScanB);
    fill_kernel<<<edgeB, 256>>>(src, dst, start, spine, cur, col, E);

    // Fused layers (launches 6-8)
    layer_kernel<64, true ><<<layerB, 256>>>((const float4*)x,  start, spine, deg, col, Wl1, Wr1, b1, h1,  N);
    layer_kernel<64, true ><<<layerB, 256>>>((const float4*)h1, start, spine, deg, col, Wl2, Wr2, b2, h2,  N);
    layer_kernel<40, false><<<layerB, 256>>>((const float4*)h2, start, spine, deg, col, Wl3, Wr3, b3, out, N);

    // log_softmax (launch 9)
    lsm_kernel<<<(N * 32 + 255) / 256, 256>>>(out, N);
}